// round 1
// baseline (speedup 1.0000x reference)
#include <cuda_runtime.h>

// BKT_RNN: T=1024 timesteps, B=4096 independent chains, H=4 hidden.
// One thread per chain. 128 blocks x 32 threads = 4096 threads.
//
// Math transforms (exact up to fp rounding):
//  1) BKT m_t == latent identically (denominators equal correct / 1-correct),
//     so latent_{t+1} = latent*(1-f-l) + l, correct = latent*(1-s-g) + g.
//  2) r-form tanh: h = 1 - 2r, r = 1/(exp(2z)+1). Recurrence kept in r with
//     pre-scaled weights; params p_j = 1 - r_j directly.

#define Tn 1024
#define Bn 4096
#define NBLK 128
#define NTHR 32

__device__ float g_part[NBLK];

__device__ __forceinline__ float ex2_f(float a){ float r; asm("ex2.approx.f32 %0, %1;" : "=f"(r) : "f"(a)); return r; }
__device__ __forceinline__ float rcp_f(float a){ float r; asm("rcp.approx.f32 %0, %1;" : "=f"(r) : "f"(a)); return r; }
__device__ __forceinline__ float lg2_f(float a){ float r; asm("lg2.approx.f32 %0, %1;" : "=f"(r) : "f"(a)); return r; }

__global__ __launch_bounds__(NTHR, 1) void bkt_main(
    const float* __restrict__ x, const float* __restrict__ y,
    const float* __restrict__ prior,
    const float* __restrict__ W_ih, const float* __restrict__ W_hh,
    const float* __restrict__ b_ih, const float* __restrict__ b_hh,
    float* __restrict__ out)
{
    const int b = blockIdx.x * NTHR + threadIdx.x;
    const float L2E2 = 2.8853900817779268f;   // 2*log2(e)

    // Pre-scaled weights (broadcast loads, amortized over 1024 steps)
    float C0[4], Cx[4], Wp[4][4];
    #pragma unroll
    for (int j = 0; j < 4; j++) {
        float S = 0.f;
        #pragma unroll
        for (int k = 0; k < 4; k++) {
            float w = W_hh[j * 4 + k];
            Wp[j][k] = -2.f * L2E2 * w;      // -4*log2e*W  (matvec over r)
            S += w;
        }
        C0[j] = L2E2 * (b_ih[j] + b_hh[j] + S);
        Cx[j] = L2E2 * W_ih[j];
    }

    // latent0 = sigmoid(prior)
    float pz = prior[0];
    float latent = 1.f / (1.f + ex2_f(-pz * 1.4426950408889634f));

    const float* xp = x + b;
    const float* yp = y + b;
    float* __restrict__ oc = out + b;              // corrects [0, T*B)
    float* __restrict__ ol = out + (size_t)Tn * Bn + b; // latents [T*B, 2*T*B)

    float r0 = 0.5f, r1 = 0.5f, r2 = 0.5f, r3 = 0.5f;  // h=0 -> r=0.5
    float lacc = 0.f;

    float xA[8], yA[8], xB[8], yB[8];
    #pragma unroll
    for (int u = 0; u < 8; u++) { xA[u] = xp[u * Bn]; yA[u] = yp[u * Bn]; }

    auto step = [&](float xv, float yv, int t) {
        // RNN step in r-domain (uses previous r0..r3)
        float u0 = fmaf(xv, Cx[0], C0[0]);
        float u1 = fmaf(xv, Cx[1], C0[1]);
        float u2 = fmaf(xv, Cx[2], C0[2]);
        float u3 = fmaf(xv, Cx[3], C0[3]);
        u0 = fmaf(r0, Wp[0][0], u0); u1 = fmaf(r0, Wp[1][0], u1);
        u2 = fmaf(r0, Wp[2][0], u2); u3 = fmaf(r0, Wp[3][0], u3);
        u0 = fmaf(r1, Wp[0][1], u0); u1 = fmaf(r1, Wp[1][1], u1);
        u2 = fmaf(r1, Wp[2][1], u2); u3 = fmaf(r1, Wp[3][1], u3);
        u0 = fmaf(r2, Wp[0][2], u0); u1 = fmaf(r2, Wp[1][2], u1);
        u2 = fmaf(r2, Wp[2][2], u2); u3 = fmaf(r2, Wp[3][2], u3);
        u0 = fmaf(r3, Wp[0][3], u0); u1 = fmaf(r3, Wp[1][3], u1);
        u2 = fmaf(r3, Wp[2][3], u2); u3 = fmaf(r3, Wp[3][3], u3);
        float E0 = ex2_f(u0), E1 = ex2_f(u1), E2 = ex2_f(u2), E3 = ex2_f(u3);
        r0 = rcp_f(E0 + 1.f);
        r1 = rcp_f(E1 + 1.f);
        r2 = rcp_f(E2 + 1.f);
        r3 = rcp_f(E3 + 1.f);

        // BKT (params: l=1-r0, f=1-r1, g=1-r2, s=1-r3)
        float g = 1.f - r2;
        float Ac = (r3 + r2) - 1.f;                 // (1-s) - g
        float correct = fmaf(latent, Ac, g);
        float omc     = fmaf(-latent, Ac, r2);      // 1 - correct (1-g = r2)
        float l = 1.f - r0;
        float Al = (r1 + r0) - 1.f;                 // (1-f) - l
        float latn = fmaf(latent, Al, l);

        // BCE: pe = y ? correct : (1-correct)
        float dcm = correct - omc;
        float pe = fmaf(yv, dcm, omc);
        float ll = lg2_f(pe) * 0.69314718055994531f;
        ll = fmaxf(ll, -100.f);
        lacc += ll;

        oc[(size_t)t * Bn] = correct;
        ol[(size_t)t * Bn] = latn;
        latent = latn;
    };

    for (int t0 = 0; t0 < Tn; t0 += 16) {
        // prefetch steps t0+8 .. t0+15 (always in range: t0 <= 1008)
        {
            const float* xq = xp + (size_t)(t0 + 8) * Bn;
            const float* yq = yp + (size_t)(t0 + 8) * Bn;
            #pragma unroll
            for (int u = 0; u < 8; u++) { xB[u] = xq[u * Bn]; yB[u] = yq[u * Bn]; }
        }
        #pragma unroll
        for (int u = 0; u < 8; u++) step(xA[u], yA[u], t0 + u);

        if (t0 + 16 < Tn) {
            const float* xq = xp + (size_t)(t0 + 16) * Bn;
            const float* yq = yp + (size_t)(t0 + 16) * Bn;
            #pragma unroll
            for (int u = 0; u < 8; u++) { xA[u] = xq[u * Bn]; yA[u] = yq[u * Bn]; }
        }
        #pragma unroll
        for (int u = 0; u < 8; u++) step(xB[u], yB[u], t0 + 8 + u);
    }

    // Deterministic loss partial: warp reduce -> per-block slot
    #pragma unroll
    for (int o = 16; o; o >>= 1) lacc += __shfl_xor_sync(0xffffffffu, lacc, o);
    if (threadIdx.x == 0) g_part[blockIdx.x] = lacc;
}

__global__ void bkt_loss(float* __restrict__ out)
{
    __shared__ float sm[4];
    int tid = threadIdx.x;
    float v = g_part[tid];                  // 128 partials, 128 threads
    #pragma unroll
    for (int o = 16; o; o >>= 1) v += __shfl_xor_sync(0xffffffffu, v, o);
    if ((tid & 31) == 0) sm[tid >> 5] = v;
    __syncthreads();
    if (tid == 0) {
        float t = sm[0] + sm[1] + sm[2] + sm[3];
        out[(size_t)2 * Tn * Bn] = -t / (float)((size_t)Tn * Bn);
    }
}

extern "C" void kernel_launch(void* const* d_in, const int* in_sizes, int n_in,
                              void* d_out, int out_size)
{
    (void)in_sizes; (void)n_in; (void)out_size;
    const float* x     = (const float*)d_in[0];
    const float* y     = (const float*)d_in[1];
    const float* prior = (const float*)d_in[2];
    const float* W_ih  = (const float*)d_in[3];
    const float* W_hh  = (const float*)d_in[4];
    const float* b_ih  = (const float*)d_in[5];
    const float* b_hh  = (const float*)d_in[6];
    float* out = (float*)d_out;

    bkt_main<<<NBLK, NTHR>>>(x, y, prior, W_ih, W_hh, b_ih, b_hh, out);
    bkt_loss<<<1, 128>>>(out);
}